// round 1
// baseline (speedup 1.0000x reference)
#include <cuda_runtime.h>
#include <math.h>

#define NE      50000
#define DIM     64
#define NREL    400
#define NLAYERS 3
#define BS      4
#define NEDGE   400000
#define MAXSLOTS (BS * NE)

// ---------------- persistent device scratch (static, no allocation) ----------
__device__ float        g_h[MAXSLOTS * DIM];     // 51.2 MB: h for active slots
__device__ float        g_agg[MAXSLOTS * DIM];   // 51.2 MB: message accumulator
__device__ int          g_slotmap[BS * NE];      // slot+1, 0 = inactive
__device__ unsigned int g_mask[NE];              // bit b = node active in batch b
__device__ int          g_elist[BS * NEDGE];     // packed (edge<<2)|b
__device__ int          g_nlist[MAXSLOTS];       // packed (node<<2)|b
__device__ int          g_cnt[8];                // 0: nSlots, 1: nNodes, 2+l: active edges layer l

// ---------------- reset per launch ----------------
__global__ void k_zero() {
    int i = blockIdx.x * blockDim.x + threadIdx.x;
    int stride = gridDim.x * blockDim.x;
    for (int j = i; j < BS * NE; j += stride) g_slotmap[j] = 0;
    for (int j = i; j < NE; j += stride) g_mask[j] = 0u;
    if (i < 8) g_cnt[i] = 0;
}

// ---------------- seed the 4 source nodes ----------------
__global__ void k_seed(const float* __restrict__ ent, const float* __restrict__ qemb,
                       const int* __restrict__ source, const int* __restrict__ qrel) {
    int w = threadIdx.x >> 5, lane = threadIdx.x & 31;
    if (w < BS) {
        int n = source[w];
        int r = qrel[w];
        if (lane == 0) {
            g_slotmap[w * NE + n] = w + 1;          // slot = batch index
            atomicOr(&g_mask[n], 1u << w);
            g_nlist[w] = (n << 2) | w;
        }
        g_h[w * DIM + lane]      = ent[n * DIM + lane]      + qemb[r * DIM + lane];
        g_h[w * DIM + lane + 32] = ent[n * DIM + lane + 32] + qemb[r * DIM + lane + 32];
        g_agg[w * DIM + lane] = 0.f;
        g_agg[w * DIM + lane + 32] = 0.f;
    }
    if (threadIdx.x == 0) { g_cnt[0] = BS; g_cnt[1] = BS; }
}

// ---------------- per-layer: find edges with active source ----------------
__global__ void k_scan(const int* __restrict__ esrc, int layer) {
    int i = blockIdx.x * blockDim.x + threadIdx.x;
    int stride = gridDim.x * blockDim.x;
    for (int e = i; e < NEDGE; e += stride) {
        unsigned m = g_mask[esrc[e]];
        while (m) {
            int b = __ffs((int)m) - 1;
            m &= m - 1;
            int pos = atomicAdd(&g_cnt[2 + layer], 1);
            g_elist[pos] = (e << 2) | b;
        }
    }
}

// ---------------- per-layer: activate targets, allocate slots ----------------
__global__ void k_activate(const int* __restrict__ etgt, int layer) {
    int total = g_cnt[2 + layer];
    int i = blockIdx.x * blockDim.x + threadIdx.x;
    int stride = gridDim.x * blockDim.x;
    for (int idx = i; idx < total; idx += stride) {
        int p = g_elist[idx];
        int e = p >> 2, b = p & 3;
        int t = etgt[e];
        unsigned bit = 1u << b;
        if (!(g_mask[t] & bit)) {                        // cheap pre-filter
            unsigned old = atomicOr(&g_mask[t], bit);
            if (!(old & bit)) {                          // we claimed it
                int slot = atomicAdd(&g_cnt[0], 1);
                g_slotmap[b * NE + t] = slot + 1;
                #pragma unroll
                for (int k = 0; k < DIM; k++) {
                    g_h[slot * DIM + k] = 0.f;
                    g_agg[slot * DIM + k] = 0.f;
                }
                int ni = atomicAdd(&g_cnt[1], 1);
                g_nlist[ni] = (t << 2) | b;
            }
        }
    }
}

// ---------------- per-layer: messages (warp per active edge) ----------------
__global__ void k_msg(const int* __restrict__ esrc, const int* __restrict__ etgt,
                      const int* __restrict__ erel,
                      const float* __restrict__ msgW, const float* __restrict__ gateW,
                      const float* __restrict__ rele, int layer) {
    __shared__ float sM[DIM * DIM];
    __shared__ float sG[DIM * DIM];
    __shared__ float sh[8][DIM];
    for (int i = threadIdx.x; i < DIM * DIM; i += blockDim.x) {
        sM[i] = msgW[layer * DIM * DIM + i];
        sG[i] = gateW[layer * DIM * DIM + i];
    }
    __syncthreads();
    int total = g_cnt[2 + layer];
    int gw = (blockIdx.x * blockDim.x + threadIdx.x) >> 5;
    int lane = threadIdx.x & 31;
    int wl = threadIdx.x >> 5;
    int nw = (gridDim.x * blockDim.x) >> 5;
    for (int idx = gw; idx < total; idx += nw) {
        int p = g_elist[idx];
        int e = p >> 2, b = p & 3;
        int s = esrc[e], t = etgt[e], r = erel[e];
        int ss = g_slotmap[b * NE + s] - 1;
        int ts = g_slotmap[b * NE + t] - 1;
        sh[wl][lane]      = g_h[ss * DIM + lane];
        sh[wl][lane + 32] = g_h[ss * DIM + lane + 32];
        __syncwarp();
        float m0 = 0.f, m1 = 0.f, q0 = 0.f, q1 = 0.f;
        #pragma unroll 8
        for (int k = 0; k < DIM; k++) {
            float hk = sh[wl][k];
            m0 = fmaf(hk, sM[k * DIM + lane],      m0);
            m1 = fmaf(hk, sM[k * DIM + lane + 32], m1);
            q0 = fmaf(hk, sG[k * DIM + lane],      q0);
            q1 = fmaf(hk, sG[k * DIM + lane + 32], q1);
        }
        const float* rr = rele + (size_t)(layer * NREL + r) * DIM;
        float v0 = m0 * rr[lane]      * (1.f / (1.f + expf(-q0)));
        float v1 = m1 * rr[lane + 32] * (1.f / (1.f + expf(-q1)));
        atomicAdd(&g_agg[ts * DIM + lane],      v0);
        atomicAdd(&g_agg[ts * DIM + lane + 32], v1);
        __syncwarp();
    }
}

// ---------------- per-layer: node update + layernorm (warp per active node) --
__global__ void k_update(const float* __restrict__ updW, const float* __restrict__ updb,
                         const float* __restrict__ lng, const float* __restrict__ lnb,
                         int layer) {
    __shared__ float sW[2 * DIM * DIM];   // 32 KB
    __shared__ float sx[8][2 * DIM];
    for (int i = threadIdx.x; i < 2 * DIM * DIM; i += blockDim.x)
        sW[i] = updW[layer * 2 * DIM * DIM + i];
    __syncthreads();
    int total = g_cnt[1];
    int gw = (blockIdx.x * blockDim.x + threadIdx.x) >> 5;
    int lane = threadIdx.x & 31;
    int wl = threadIdx.x >> 5;
    int nw = (gridDim.x * blockDim.x) >> 5;
    for (int idx = gw; idx < total; idx += nw) {
        int p = g_nlist[idx];
        int n = p >> 2, b = p & 3;
        int slot = g_slotmap[b * NE + n] - 1;
        float h0 = g_h[slot * DIM + lane],   h1 = g_h[slot * DIM + lane + 32];
        float a0 = g_agg[slot * DIM + lane], a1 = g_agg[slot * DIM + lane + 32];
        sx[wl][lane] = h0; sx[wl][lane + 32] = h1;
        sx[wl][64 + lane] = a0; sx[wl][96 + lane] = a1;
        __syncwarp();
        float u0 = updb[layer * DIM + lane], u1 = updb[layer * DIM + lane + 32];
        #pragma unroll 8
        for (int k = 0; k < 2 * DIM; k++) {
            float xk = sx[wl][k];
            u0 = fmaf(xk, sW[k * DIM + lane],      u0);
            u1 = fmaf(xk, sW[k * DIM + lane + 32], u1);
        }
        u0 = fmaxf(u0, 0.f); u1 = fmaxf(u1, 0.f);
        float x0 = h0 + u0, x1 = h1 + u1;
        float s = x0 + x1;
        #pragma unroll
        for (int o = 16; o > 0; o >>= 1) s += __shfl_xor_sync(0xffffffffu, s, o);
        float mean = s * (1.f / 64.f);
        float d0 = x0 - mean, d1 = x1 - mean;
        float v = d0 * d0 + d1 * d1;
        #pragma unroll
        for (int o = 16; o > 0; o >>= 1) v += __shfl_xor_sync(0xffffffffu, v, o);
        float inv = rsqrtf(v * (1.f / 64.f) + 1e-5f);
        g_h[slot * DIM + lane]      = d0 * inv * lng[layer * DIM + lane]      + lnb[layer * DIM + lane];
        g_h[slot * DIM + lane + 32] = d1 * inv * lng[layer * DIM + lane + 32] + lnb[layer * DIM + lane + 32];
        g_agg[slot * DIM + lane] = 0.f;
        g_agg[slot * DIM + lane + 32] = 0.f;
        __syncwarp();
    }
}

// ---------------- background score: h = 0, score depends only on ent_emb ----
__global__ void k_bg(const float* __restrict__ ent, const float* __restrict__ sW1,
                     const float* __restrict__ sb1, const float* __restrict__ sW2,
                     const float* __restrict__ sb2, float* __restrict__ out) {
    __shared__ float2 sw[DIM * 32];   // sw[k*32+j] = (W1[64+k][j], W1[64+k][j+32])
    __shared__ float sb[DIM];
    __shared__ float sv[DIM];
    __shared__ float te[8][DIM];
    for (int i = threadIdx.x; i < DIM * 32; i += blockDim.x) {
        int k = i >> 5, j = i & 31;
        sw[i] = make_float2(sW1[(DIM + k) * DIM + j], sW1[(DIM + k) * DIM + j + 32]);
    }
    for (int i = threadIdx.x; i < DIM; i += blockDim.x) { sb[i] = sb1[i]; sv[i] = sW2[i]; }
    __syncthreads();
    float b2 = sb2[0];
    int gw = (blockIdx.x * blockDim.x + threadIdx.x) >> 5;
    int lane = threadIdx.x & 31;
    int wl = threadIdx.x >> 5;
    int nw = (gridDim.x * blockDim.x) >> 5;
    for (int n = gw; n < NE; n += nw) {
        te[wl][lane]      = ent[n * DIM + lane];
        te[wl][lane + 32] = ent[n * DIM + lane + 32];
        __syncwarp();
        float s0 = sb[lane], s1 = sb[lane + 32];
        #pragma unroll 8
        for (int k = 0; k < DIM; k++) {
            float tk = te[wl][k];
            float2 wv = sw[k * 32 + lane];
            s0 = fmaf(tk, wv.x, s0);
            s1 = fmaf(tk, wv.y, s1);
        }
        s0 = fmaxf(s0, 0.f); s1 = fmaxf(s1, 0.f);
        float acc = s0 * sv[lane] + s1 * sv[lane + 32];
        #pragma unroll
        for (int o = 16; o > 0; o >>= 1) acc += __shfl_xor_sync(0xffffffffu, acc, o);
        if (lane == 0) {
            float o = acc + b2;
            out[0 * NE + n] = o; out[1 * NE + n] = o;
            out[2 * NE + n] = o; out[3 * NE + n] = o;
        }
        __syncwarp();
    }
}

// ---------------- active-node score: full [h, te] @ sW1 ----------------
__global__ void k_actscore(const float* __restrict__ ent, const float* __restrict__ sW1,
                           const float* __restrict__ sb1, const float* __restrict__ sW2,
                           const float* __restrict__ sb2, float* __restrict__ out) {
    __shared__ float2 sw[2 * DIM * 32];  // 32 KB: all 128 rows of sW1, column pairs
    __shared__ float sb[DIM];
    __shared__ float sv[DIM];
    __shared__ float sx[8][2 * DIM];
    for (int i = threadIdx.x; i < 2 * DIM * 32; i += blockDim.x) {
        int k = i >> 5, j = i & 31;
        sw[i] = make_float2(sW1[k * DIM + j], sW1[k * DIM + j + 32]);
    }
    for (int i = threadIdx.x; i < DIM; i += blockDim.x) { sb[i] = sb1[i]; sv[i] = sW2[i]; }
    __syncthreads();
    float b2 = sb2[0];
    int total = g_cnt[1];
    int gw = (blockIdx.x * blockDim.x + threadIdx.x) >> 5;
    int lane = threadIdx.x & 31;
    int wl = threadIdx.x >> 5;
    int nw = (gridDim.x * blockDim.x) >> 5;
    for (int idx = gw; idx < total; idx += nw) {
        int p = g_nlist[idx];
        int n = p >> 2, b = p & 3;
        int slot = g_slotmap[b * NE + n] - 1;
        sx[wl][lane]      = g_h[slot * DIM + lane];
        sx[wl][lane + 32] = g_h[slot * DIM + lane + 32];
        sx[wl][64 + lane] = ent[n * DIM + lane];
        sx[wl][96 + lane] = ent[n * DIM + lane + 32];
        __syncwarp();
        float s0 = sb[lane], s1 = sb[lane + 32];
        #pragma unroll 8
        for (int k = 0; k < 2 * DIM; k++) {
            float xk = sx[wl][k];
            float2 wv = sw[k * 32 + lane];
            s0 = fmaf(xk, wv.x, s0);
            s1 = fmaf(xk, wv.y, s1);
        }
        s0 = fmaxf(s0, 0.f); s1 = fmaxf(s1, 0.f);
        float acc = s0 * sv[lane] + s1 * sv[lane + 32];
        #pragma unroll
        for (int o = 16; o > 0; o >>= 1) acc += __shfl_xor_sync(0xffffffffu, acc, o);
        if (lane == 0) out[b * NE + n] = acc + b2;
        __syncwarp();
    }
}

extern "C" void kernel_launch(void* const* d_in, const int* in_sizes, int n_in,
                              void* d_out, int out_size) {
    const float* ent   = (const float*)d_in[0];
    const float* qemb  = (const float*)d_in[1];
    const float* rele  = (const float*)d_in[2];
    const float* msgW  = (const float*)d_in[3];
    const float* gateW = (const float*)d_in[4];
    const float* updW  = (const float*)d_in[5];
    const float* updb  = (const float*)d_in[6];
    const float* lng   = (const float*)d_in[7];
    const float* lnb   = (const float*)d_in[8];
    const float* sW1   = (const float*)d_in[9];
    const float* sb1   = (const float*)d_in[10];
    const float* sW2   = (const float*)d_in[11];
    const float* sb2   = (const float*)d_in[12];
    const int* source  = (const int*)d_in[13];
    const int* qrel    = (const int*)d_in[14];
    const int* esrc    = (const int*)d_in[15];
    const int* etgt    = (const int*)d_in[16];
    const int* erel    = (const int*)d_in[17];
    float* out = (float*)d_out;

    k_zero<<<400, 256>>>();
    k_seed<<<1, 256>>>(ent, qemb, source, qrel);
    for (int l = 0; l < NLAYERS; l++) {
        k_scan<<<1024, 256>>>(esrc, l);
        k_activate<<<512, 256>>>(etgt, l);
        k_msg<<<512, 256>>>(esrc, etgt, erel, msgW, gateW, rele, l);
        k_update<<<512, 256>>>(updW, updb, lng, lnb, l);
    }
    k_bg<<<296, 256>>>(ent, sW1, sb1, sW2, sb2, out);
    k_actscore<<<512, 256>>>(ent, sW1, sb1, sW2, sb2, out);
}

// round 2
// speedup vs baseline: 1.2219x; 1.2219x over previous
#include <cuda_runtime.h>
#include <math.h>

#define NE      50000
#define DIM     64
#define NREL    400
#define NLAYERS 3
#define BS      4
#define NEDGE   400000
#define MAXSLOTS (BS * NE)
#define FULL 0xffffffffu

// ---------------- persistent device scratch (static, no allocation) ----------
__device__ float        g_h[MAXSLOTS * DIM];     // h for active slots
__device__ float        g_agg[MAXSLOTS * DIM];   // message accumulator
__device__ int          g_slotmap[BS * NE];      // slot+1, 0 = free, -1 = claim in progress
__device__ unsigned int g_mask[NE];              // bit b = node active (at layer start)
__device__ int          g_nlist[MAXSLOTS];       // packed (node<<2)|b
__device__ int          g_cnt[4];                // 0: slot alloc, 1: nlist count

// ---------------- reset per launch ----------------
__global__ void k_zero() {
    int i = blockIdx.x * blockDim.x + threadIdx.x;
    int stride = gridDim.x * blockDim.x;
    for (int j = i; j < BS * NE; j += stride) g_slotmap[j] = 0;
    for (int j = i; j < NE; j += stride) g_mask[j] = 0u;
    if (i < 4) g_cnt[i] = 0;
}

// ---------------- seed the BS source nodes ----------------
__global__ void k_seed(const float* __restrict__ ent, const float* __restrict__ qemb,
                       const int* __restrict__ source, const int* __restrict__ qrel) {
    int w = threadIdx.x >> 5, lane = threadIdx.x & 31;
    if (w < BS) {
        int n = source[w];
        int r = qrel[w];
        if (lane == 0) {
            g_slotmap[w * NE + n] = w + 1;          // slot = batch index
            atomicOr(&g_mask[n], 1u << w);
            g_nlist[w] = (n << 2) | w;
        }
        g_h[w * DIM + lane]      = ent[n * DIM + lane]      + qemb[r * DIM + lane];
        g_h[w * DIM + lane + 32] = ent[n * DIM + lane + 32] + qemb[r * DIM + lane + 32];
        g_agg[w * DIM + lane] = 0.f;
        g_agg[w * DIM + lane + 32] = 0.f;
    }
    if (threadIdx.x == 0) { g_cnt[0] = BS; g_cnt[1] = BS; }
}

// ---------------- per-layer fused: scan + activate + message -----------------
// Phase A: each thread tests one edge against the (stable) g_mask snapshot and
// pushes active (edge,batch) pairs into a block-shared queue.
// Phase B: warps drain the queue: claim/spin target slot, matvec, atomic scatter.
__global__ void k_edge(const int* __restrict__ esrc, const int* __restrict__ etgt,
                       const int* __restrict__ erel,
                       const float* __restrict__ msgW, const float* __restrict__ gateW,
                       const float* __restrict__ rele, int layer) {
    __shared__ float sM[DIM * DIM];
    __shared__ float sG[DIM * DIM];
    __shared__ int   q[256 * BS];
    __shared__ int   qn;
    __shared__ float sh[8][DIM];
    for (int i = threadIdx.x; i < DIM * DIM; i += blockDim.x) {
        sM[i] = msgW[layer * DIM * DIM + i];
        sG[i] = gateW[layer * DIM * DIM + i];
    }
    int lane = threadIdx.x & 31;
    int wl   = threadIdx.x >> 5;

    for (int base = blockIdx.x * 256; base < NEDGE; base += gridDim.x * 256) {
        if (threadIdx.x == 0) qn = 0;
        __syncthreads();
        int e = base + threadIdx.x;
        if (e < NEDGE) {
            unsigned m = g_mask[esrc[e]];
            while (m) {
                int b = __ffs((int)m) - 1;
                m &= m - 1;
                int pos = atomicAdd(&qn, 1);
                q[pos] = (e << 2) | b;
            }
        }
        __syncthreads();
        int total = qn;
        for (int idx = wl; idx < total; idx += 8) {
            int p = q[idx];
            int e2 = p >> 2, b = p & 3;
            int s = esrc[e2], t = etgt[e2], r = erel[e2];
            int ss = g_slotmap[b * NE + s] - 1;

            // --- claim / resolve target slot ---
            int* sp = &g_slotmap[b * NE + t];
            int cur;
            if (lane == 0) cur = atomicCAS(sp, 0, -1);
            cur = __shfl_sync(FULL, cur, 0);
            int ts;
            if (cur == 0) {                       // this warp claimed the slot
                int slot;
                if (lane == 0) slot = atomicAdd(&g_cnt[0], 1);
                slot = __shfl_sync(FULL, slot, 0);
                g_h[slot * DIM + lane] = 0.f;       g_h[slot * DIM + lane + 32] = 0.f;
                g_agg[slot * DIM + lane] = 0.f;     g_agg[slot * DIM + lane + 32] = 0.f;
                __syncwarp();
                __threadfence();
                if (lane == 0) {
                    int ni = atomicAdd(&g_cnt[1], 1);
                    g_nlist[ni] = (t << 2) | b;
                    atomicExch(sp, slot + 1);       // publish
                }
                ts = slot;
            } else if (cur > 0) {
                ts = cur - 1;
            } else {                               // another warp is initializing: spin
                if (lane == 0) { do { cur = atomicAdd(sp, 0); } while (cur <= 0); }
                cur = __shfl_sync(FULL, cur, 0);
                ts = cur - 1;
            }

            // --- message matvec ---
            sh[wl][lane]      = g_h[ss * DIM + lane];
            sh[wl][lane + 32] = g_h[ss * DIM + lane + 32];
            __syncwarp();
            float m0 = 0.f, m1 = 0.f, q0 = 0.f, q1 = 0.f;
            #pragma unroll 8
            for (int k = 0; k < DIM; k++) {
                float hk = sh[wl][k];
                m0 = fmaf(hk, sM[k * DIM + lane],      m0);
                m1 = fmaf(hk, sM[k * DIM + lane + 32], m1);
                q0 = fmaf(hk, sG[k * DIM + lane],      q0);
                q1 = fmaf(hk, sG[k * DIM + lane + 32], q1);
            }
            const float* rr = rele + (size_t)(layer * NREL + r) * DIM;
            float v0 = m0 * rr[lane]      * (1.f / (1.f + expf(-q0)));
            float v1 = m1 * rr[lane + 32] * (1.f / (1.f + expf(-q1)));
            atomicAdd(&g_agg[ts * DIM + lane],      v0);
            atomicAdd(&g_agg[ts * DIM + lane + 32], v1);
            __syncwarp();
        }
        __syncthreads();
    }
}

// ---------------- per-layer: node update + layernorm (warp per active node) --
// Also commits this layer's new activations into g_mask (idempotent atomicOr).
__global__ void k_update(const float* __restrict__ updW, const float* __restrict__ updb,
                         const float* __restrict__ lng, const float* __restrict__ lnb,
                         int layer) {
    __shared__ float sW[2 * DIM * DIM];   // 32 KB
    __shared__ float sx[8][2 * DIM];
    for (int i = threadIdx.x; i < 2 * DIM * DIM; i += blockDim.x)
        sW[i] = updW[layer * 2 * DIM * DIM + i];
    __syncthreads();
    int total = g_cnt[1];
    int gw = (blockIdx.x * blockDim.x + threadIdx.x) >> 5;
    int lane = threadIdx.x & 31;
    int wl = threadIdx.x >> 5;
    int nw = (gridDim.x * blockDim.x) >> 5;
    for (int idx = gw; idx < total; idx += nw) {
        int p = g_nlist[idx];
        int n = p >> 2, b = p & 3;
        int slot = g_slotmap[b * NE + n] - 1;
        if (lane == 0) atomicOr(&g_mask[n], 1u << b);   // commit activation
        float h0 = g_h[slot * DIM + lane],   h1 = g_h[slot * DIM + lane + 32];
        float a0 = g_agg[slot * DIM + lane], a1 = g_agg[slot * DIM + lane + 32];
        sx[wl][lane] = h0; sx[wl][lane + 32] = h1;
        sx[wl][64 + lane] = a0; sx[wl][96 + lane] = a1;
        __syncwarp();
        float u0 = updb[layer * DIM + lane], u1 = updb[layer * DIM + lane + 32];
        #pragma unroll 8
        for (int k = 0; k < 2 * DIM; k++) {
            float xk = sx[wl][k];
            u0 = fmaf(xk, sW[k * DIM + lane],      u0);
            u1 = fmaf(xk, sW[k * DIM + lane + 32], u1);
        }
        u0 = fmaxf(u0, 0.f); u1 = fmaxf(u1, 0.f);
        float x0 = h0 + u0, x1 = h1 + u1;
        float s = x0 + x1;
        #pragma unroll
        for (int o = 16; o > 0; o >>= 1) s += __shfl_xor_sync(FULL, s, o);
        float mean = s * (1.f / 64.f);
        float d0 = x0 - mean, d1 = x1 - mean;
        float v = d0 * d0 + d1 * d1;
        #pragma unroll
        for (int o = 16; o > 0; o >>= 1) v += __shfl_xor_sync(FULL, v, o);
        float inv = rsqrtf(v * (1.f / 64.f) + 1e-5f);
        g_h[slot * DIM + lane]      = d0 * inv * lng[layer * DIM + lane]      + lnb[layer * DIM + lane];
        g_h[slot * DIM + lane + 32] = d1 * inv * lng[layer * DIM + lane + 32] + lnb[layer * DIM + lane + 32];
        g_agg[slot * DIM + lane] = 0.f;
        g_agg[slot * DIM + lane + 32] = 0.f;
        __syncwarp();
    }
}

// ---------------- fused scoring ----------------
// Work items: nBg = ceil(NE/4) warp-items (4 background nodes each, skipping
// active (b,n) pairs via g_mask), then nAct active items (full [h,te] score).
// Every output element is written exactly once.
__global__ void k_score(const float* __restrict__ ent, const float* __restrict__ sW1,
                        const float* __restrict__ sb1, const float* __restrict__ sW2,
                        const float* __restrict__ sb2, float* __restrict__ out) {
    __shared__ float2 sw[2 * DIM * 32];  // 32 KB: sw[k*32+j] = (W1[k][j], W1[k][j+32]), k in 0..127
    __shared__ float sb[DIM];
    __shared__ float sv[DIM];
    __shared__ float te[8][4 * DIM];     // 8 KB staging
    for (int i = threadIdx.x; i < 2 * DIM * 32; i += blockDim.x) {
        int k = i >> 5, j = i & 31;
        sw[i] = make_float2(sW1[k * DIM + j], sW1[k * DIM + j + 32]);
    }
    for (int i = threadIdx.x; i < DIM; i += blockDim.x) { sb[i] = sb1[i]; sv[i] = sW2[i]; }
    __syncthreads();
    float b2 = sb2[0];
    int nAct = g_cnt[1];
    const int nBg = (NE + 3) / 4;
    int W = nBg + nAct;
    int gw = (blockIdx.x * blockDim.x + threadIdx.x) >> 5;
    int lane = threadIdx.x & 31;
    int wl = threadIdx.x >> 5;
    int nw = (gridDim.x * blockDim.x) >> 5;
    for (int w = gw; w < W; w += nw) {
        if (w < nBg) {
            // ---- background: 4 nodes, h = 0 → only rows [64,128) of sW1 ----
            int n0 = w * 4;
            int nvalid = min(4, NE - n0);
            #pragma unroll
            for (int j = 0; j < 4; j++) {
                if (j < nvalid) {
                    te[wl][j * DIM + lane]      = ent[(n0 + j) * DIM + lane];
                    te[wl][j * DIM + lane + 32] = ent[(n0 + j) * DIM + lane + 32];
                }
            }
            __syncwarp();
            float s0[4], s1[4];
            #pragma unroll
            for (int j = 0; j < 4; j++) { s0[j] = sb[lane]; s1[j] = sb[lane + 32]; }
            #pragma unroll 4
            for (int k = 0; k < DIM; k++) {
                float2 wv = sw[(DIM + k) * 32 + lane];
                #pragma unroll
                for (int j = 0; j < 4; j++) {
                    float t = te[wl][j * DIM + k];
                    s0[j] = fmaf(t, wv.x, s0[j]);
                    s1[j] = fmaf(t, wv.y, s1[j]);
                }
            }
            #pragma unroll
            for (int j = 0; j < 4; j++) {
                float a = fmaxf(s0[j], 0.f) * sv[lane] + fmaxf(s1[j], 0.f) * sv[lane + 32];
                #pragma unroll
                for (int o = 16; o > 0; o >>= 1) a += __shfl_xor_sync(FULL, a, o);
                if (lane == 0 && j < nvalid) {
                    int n = n0 + j;
                    float sc = a + b2;
                    unsigned m = g_mask[n];
                    if (!(m & 1u)) out[0 * NE + n] = sc;
                    if (!(m & 2u)) out[1 * NE + n] = sc;
                    if (!(m & 4u)) out[2 * NE + n] = sc;
                    if (!(m & 8u)) out[3 * NE + n] = sc;
                }
            }
            __syncwarp();
        } else {
            // ---- active (b,n): full [h, te] @ sW1 ----
            int p = g_nlist[w - nBg];
            int n = p >> 2, b = p & 3;
            int slot = g_slotmap[b * NE + n] - 1;
            te[wl][lane]      = g_h[slot * DIM + lane];
            te[wl][lane + 32] = g_h[slot * DIM + lane + 32];
            te[wl][64 + lane] = ent[n * DIM + lane];
            te[wl][96 + lane] = ent[n * DIM + lane + 32];
            __syncwarp();
            float s0 = sb[lane], s1 = sb[lane + 32];
            #pragma unroll 8
            for (int k = 0; k < 2 * DIM; k++) {
                float xk = te[wl][k];
                float2 wv = sw[k * 32 + lane];
                s0 = fmaf(xk, wv.x, s0);
                s1 = fmaf(xk, wv.y, s1);
            }
            float a = fmaxf(s0, 0.f) * sv[lane] + fmaxf(s1, 0.f) * sv[lane + 32];
            #pragma unroll
            for (int o = 16; o > 0; o >>= 1) a += __shfl_xor_sync(FULL, a, o);
            if (lane == 0) out[b * NE + n] = a + b2;
            __syncwarp();
        }
    }
}

extern "C" void kernel_launch(void* const* d_in, const int* in_sizes, int n_in,
                              void* d_out, int out_size) {
    const float* ent   = (const float*)d_in[0];
    const float* qemb  = (const float*)d_in[1];
    const float* rele  = (const float*)d_in[2];
    const float* msgW  = (const float*)d_in[3];
    const float* gateW = (const float*)d_in[4];
    const float* updW  = (const float*)d_in[5];
    const float* updb  = (const float*)d_in[6];
    const float* lng   = (const float*)d_in[7];
    const float* lnb   = (const float*)d_in[8];
    const float* sW1   = (const float*)d_in[9];
    const float* sb1   = (const float*)d_in[10];
    const float* sW2   = (const float*)d_in[11];
    const float* sb2   = (const float*)d_in[12];
    const int* source  = (const int*)d_in[13];
    const int* qrel    = (const int*)d_in[14];
    const int* esrc    = (const int*)d_in[15];
    const int* etgt    = (const int*)d_in[16];
    const int* erel    = (const int*)d_in[17];
    float* out = (float*)d_out;

    k_zero<<<200, 256>>>();
    k_seed<<<1, 128>>>(ent, qemb, source, qrel);
    for (int l = 0; l < NLAYERS; l++) {
        k_edge<<<400, 256>>>(esrc, etgt, erel, msgW, gateW, rele, l);
        k_update<<<128, 256>>>(updW, updb, lng, lnb, l);
    }
    k_score<<<232, 256>>>(ent, sW1, sb1, sW2, sb2, out);
}